// round 14
// baseline (speedup 1.0000x reference)
#include <cuda_runtime.h>
#include <cuda_bf16.h>

// ---------------- problem constants ----------------
#define B_  64
#define H_  512
#define W_  512
#define RAD 20
#define KSZ 41

// ---------------- Gaussian weights (compile-time) ----------------
constexpr double PHI[21] = {
    1.0,
    0.98019867, 0.92311635, 0.83527021, 0.72614903, 0.60653066,
    0.48675227, 0.37531110, 0.27803730, 0.19789870, 0.13533528,
    0.08892161, 0.05613478, 0.03404747, 0.01984109, 0.01110900,
    0.00597603, 0.00308871, 0.00153381, 0.00073181, 0.00033546
};

constexpr double ksum() {
    double s = PHI[0];
    for (int t = 1; t <= 20; ++t) s += 2.0 * PHI[t];
    return s;
}

struct W41x2 { float2 v[KSZ]; };

constexpr W41x2 make_w2(double scale) {
    W41x2 w{};
    double s = ksum();
    for (int i = 0; i < KSZ; ++i) {
        int t = i - RAD; if (t < 0) t = -t;
        float f = (float)(scale * PHI[t] / s);
        w.v[i].x = f; w.v[i].y = f;
    }
    return w;
}

__constant__ W41x2 WH2 = make_w2(1.0);    // h-pass
__constant__ W41x2 WV2 = make_w2(100.0);  // v-pass folds 2*ALPHA; subtract ALPHA later

// packed f32x2 FMA (sm_100+)
__device__ __forceinline__ void fma2(float2& acc, const float2 v, const float2 w) {
    asm("fma.rn.f32x2 %0, %1, %2, %0;"
        : "+l"(reinterpret_cast<unsigned long long&>(acc))
        : "l"(reinterpret_cast<const unsigned long long&>(v)),
          "l"(reinterpret_cast<const unsigned long long&>(w)));
}

// ---------------- interleaved scratch: (dx,dy) pairs ----------------
__device__ float2 g_t[(size_t)B_ * H_ * W_];

__device__ __forceinline__ int reflect_once(int i, int n) {
    i = (i < 0) ? (-1 - i) : i;
    return (i >= n) ? (2 * n - 1 - i) : i;
}

// fast reflect for gather coords: valid for i in [-512, 1023], n=512
__device__ __forceinline__ int reflect_fast(int i) {
    return ((unsigned)i < (unsigned)W_) ? i : (~i & (2 * W_ - 1));
}

// ================= kernel 1: horizontal blur (R7 champion config) =================
// Tile 32 rows x 32 cols. block (32,8): threadIdx.x = row lane, ty = 4-col chunk.
// smem col-major s[cc*33 + r]; grid.x = x-tiles (consecutive CTAs share x-halo in L2).
#define HS_STR 33

__global__ __launch_bounds__(256) void hblur_kernel(
    const float* __restrict__ rdx, const float* __restrict__ rdy)
{
    __shared__ float2 s[72 * HS_STR];   // 19,008 B

    const int r   = threadIdx.x;             // 0..31 row lane
    const int ty  = threadIdx.y;             // 0..7 col chunk (4 cols each)
    const int tid = ty * 32 + r;
    const int c0   = blockIdx.x * 32;
    const int row0 = blockIdx.y * 32;
    const int b    = blockIdx.z;
    const size_t base = (size_t)b * H_ * W_;

    // halo: 72 window cols x 32 rows; div-free, coalesced on col
    {
        const int lc = tid & 31;
        const int lr = tid >> 5;             // 0..7
        #pragma unroll
        for (int q = 0; q < 3; ++q) {
            const int cc = lc + 32 * q;
            if (cc < 72) {
                const int gc = reflect_once(c0 - RAD + cc, W_);
                #pragma unroll
                for (int m = 0; m < 4; ++m) {
                    const int rr = lr + 8 * m;
                    const size_t g = base + (size_t)(row0 + rr) * W_ + gc;
                    s[cc * HS_STR + rr] = make_float2(rdx[g], rdy[g]);
                }
            }
        }
    }
    __syncthreads();

    const int x0 = ty * 4;                   // local first output col
    float2 acc[4] = {};
    float2 win[4];
    #pragma unroll
    for (int k = 0; k < 4; ++k) win[k] = s[(x0 + k) * HS_STR + r];

    #pragma unroll
    for (int t = 0; t < KSZ; ++t) {
        float2 nxt;
        if (t < KSZ - 1) nxt = s[(x0 + t + 4) * HS_STR + r];
        const float2 w = WH2.v[t];
        #pragma unroll
        for (int j = 0; j < 4; ++j)
            fma2(acc[j], win[(t + j) & 3], w);
        if (t < KSZ - 1) win[t & 3] = nxt;
    }
    __syncthreads();

    // transpose through smem: s2[r*41 + c] (conflict-free per 16-lane phase)
    float2* s2 = s;
    #pragma unroll
    for (int j = 0; j < 4; ++j)
        s2[r * 41 + x0 + j] = acc[j];
    __syncthreads();

    // coalesced stores: 32x32 tile, 4 iterations
    #pragma unroll
    for (int m = 0; m < 4; ++m) {
        const int i  = m * 256 + tid;
        const int rr = i >> 5;
        const int cc = i & 31;
        g_t[base + (size_t)(row0 + rr) * W_ + c0 + cc] = s2[rr * 41 + cc];
    }
}

// ================= kernel 2: vertical blur + warp (ring-8 conv, grid transposed) =================
// Tile 32 cols x 32 rows. block (32,8): tx = col, ty = 4-row chunk.
// GRID TRANSPOSED: blockIdx.x = y-tile, blockIdx.y = x-tile. Consecutive bids are
// y-adjacent -> share 40 of 72 g_t halo rows AND overlapping img gather rows in L2.
#define VS_STR 73

__global__ __launch_bounds__(256) void vwarp_kernel(
    const float* __restrict__ img, float* __restrict__ out)
{
    __shared__ float2 s[32 * VS_STR];   // 18,688 B

    const int tx = threadIdx.x;
    const int ty = threadIdx.y;          // 0..7
    const int x  = blockIdx.y * 32 + tx;   // transposed grid
    const int y0 = blockIdx.x * 32;        // transposed grid
    const int b  = blockIdx.z;
    const size_t base = (size_t)b * H_ * W_;
    const float2* gt = g_t + base;

    // halo: 72 rows of this block's 32 cols, coalesced on x; 9 iters
    #pragma unroll
    for (int j = ty; j < 32 + 2 * RAD; j += 8) {
        const int y = reflect_once(y0 + j - RAD, H_);
        s[tx * VS_STR + j] = __ldg(&gt[(size_t)y * W_ + x]);
    }
    __syncthreads();

    const int r0 = ty * 4;               // first output row (tile-local)
    float2 acc[4] = {};
    // ring-8 window: refill distance 5 taps covers LDS latency
    float2 win[8];
    #pragma unroll
    for (int k = 0; k < 8; ++k) win[k] = s[tx * VS_STR + r0 + k];

    #pragma unroll
    for (int t = 0; t < KSZ; ++t) {
        float2 nxt;
        if (t < 36) nxt = s[tx * VS_STR + r0 + t + 8];
        const float2 w = WV2.v[t];
        #pragma unroll
        for (int j = 0; j < 4; ++j)
            fma2(acc[j], win[(t + j) & 7], w);
        if (t < 36) win[t & 7] = nxt;
    }

    const float* im = img + base;
    const float xbase = (float)x - 50.0f;   // fold (2*ALPHA*blur - ALPHA)

    #pragma unroll
    for (int j = 0; j < 4; ++j) {
        const int yo = y0 + r0 + j;
        const float xx = xbase + acc[j].x;
        const float yy = (float)yo - 50.0f + acc[j].y;

        const int xi = __float2int_rd(xx);
        const int yi = __float2int_rd(yy);
        const float wx = xx - (float)xi;
        const float wy = yy - (float)yi;

        const int x0r = reflect_fast(xi);
        const int x1r = reflect_fast(xi + 1);
        const int y0r = reflect_fast(yi);   // H_==W_==512
        const int y1r = reflect_fast(yi + 1);

        const float* ra = im + (size_t)y0r * W_;
        const float* rb = im + (size_t)y1r * W_;
        const float v00 = __ldg(ra + x0r);
        const float v01 = __ldg(ra + x1r);
        const float v10 = __ldg(rb + x0r);
        const float v11 = __ldg(rb + x1r);

        const float top = fmaf(wx, v01 - v00, v00);
        const float bot = fmaf(wx, v11 - v10, v10);
        out[base + (size_t)yo * W_ + x] = fmaf(wy, bot - top, top);
    }
}

// ---------------- launch ----------------
extern "C" void kernel_launch(void* const* d_in, const int* in_sizes, int n_in,
                              void* d_out, int out_size)
{
    const float* x       = (const float*)d_in[0];  // [B,1,H,W]
    const float* rand_dx = (const float*)d_in[1];  // [B,H,W]
    const float* rand_dy = (const float*)d_in[2];  // [B,H,W]
    float* out = (float*)d_out;

    {
        dim3 grid(W_ / 32, H_ / 32, B_);
        dim3 block(32, 8);
        hblur_kernel<<<grid, block>>>(rand_dx, rand_dy);
    }
    {
        // transposed: grid.x = y-tiles, grid.y = x-tiles
        dim3 grid(H_ / 32, W_ / 32, B_);
        dim3 block(32, 8);
        vwarp_kernel<<<grid, block>>>(x, out);
    }
}

// round 15
// speedup vs baseline: 1.1906x; 1.1906x over previous
#include <cuda_runtime.h>
#include <cuda_bf16.h>

// ---------------- problem constants ----------------
#define B_  64
#define H_  512
#define W_  512
#define RAD 20
#define KSZ 41

// ---------------- Gaussian weights (compile-time) ----------------
constexpr double PHI[21] = {
    1.0,
    0.98019867, 0.92311635, 0.83527021, 0.72614903, 0.60653066,
    0.48675227, 0.37531110, 0.27803730, 0.19789870, 0.13533528,
    0.08892161, 0.05613478, 0.03404747, 0.01984109, 0.01110900,
    0.00597603, 0.00308871, 0.00153381, 0.00073181, 0.00033546
};

constexpr double ksum() {
    double s = PHI[0];
    for (int t = 1; t <= 20; ++t) s += 2.0 * PHI[t];
    return s;
}

struct W41x2 { float2 v[KSZ]; };

constexpr W41x2 make_w2(double scale) {
    W41x2 w{};
    double s = ksum();
    for (int i = 0; i < KSZ; ++i) {
        int t = i - RAD; if (t < 0) t = -t;
        float f = (float)(scale * PHI[t] / s);
        w.v[i].x = f; w.v[i].y = f;
    }
    return w;
}

__constant__ W41x2 WH2 = make_w2(1.0);    // h-pass
__constant__ W41x2 WV2 = make_w2(100.0);  // v-pass folds 2*ALPHA; subtract ALPHA later

// packed f32x2 FMA (sm_100+)
__device__ __forceinline__ void fma2(float2& acc, const float2 v, const float2 w) {
    asm("fma.rn.f32x2 %0, %1, %2, %0;"
        : "+l"(reinterpret_cast<unsigned long long&>(acc))
        : "l"(reinterpret_cast<const unsigned long long&>(v)),
          "l"(reinterpret_cast<const unsigned long long&>(w)));
}

// ---------------- TRANSPOSED interleaved scratch: g_tT[b][x][y] = (dx,dy) ----------------
// hblur writes it coalesced without a transpose stage; vwarp reads 72-row
// y-runs contiguously.
__device__ float2 g_tT[(size_t)B_ * H_ * W_];

__device__ __forceinline__ int reflect_once(int i, int n) {
    i = (i < 0) ? (-1 - i) : i;
    return (i >= n) ? (2 * n - 1 - i) : i;
}

// fast reflect for gather coords: valid for i in [-512, 1023], n=512
__device__ __forceinline__ int reflect_fast(int i) {
    return ((unsigned)i < (unsigned)W_) ? i : (~i & (2 * W_ - 1));
}

// ================= kernel 1: horizontal blur (R7 core, direct transposed stores) =================
// Tile 32 rows x 32 cols. block (32,8): threadIdx.x = row lane, ty = 4-col chunk.
// smem col-major s[cc*33 + r]: compute LDS.64 lane stride 8B (conflict-free).
// Output stored to g_tT[x][y]: per output col, lanes = 32 consecutive y -> 256B coalesced.
#define HS_STR 33

__global__ __launch_bounds__(256) void hblur_kernel(
    const float* __restrict__ rdx, const float* __restrict__ rdy)
{
    __shared__ float2 s[72 * HS_STR];   // 19,008 B

    const int r   = threadIdx.x;             // 0..31 row lane
    const int ty  = threadIdx.y;             // 0..7 col chunk (4 cols each)
    const int tid = ty * 32 + r;
    const int c0   = blockIdx.x * 32;
    const int row0 = blockIdx.y * 32;
    const int b    = blockIdx.z;
    const size_t base = (size_t)b * H_ * W_;

    // halo: 72 window cols x 32 rows; div-free, coalesced on col
    {
        const int lc = tid & 31;
        const int lr = tid >> 5;             // 0..7
        #pragma unroll
        for (int q = 0; q < 3; ++q) {
            const int cc = lc + 32 * q;
            if (cc < 72) {
                const int gc = reflect_once(c0 - RAD + cc, W_);
                #pragma unroll
                for (int m = 0; m < 4; ++m) {
                    const int rr = lr + 8 * m;
                    const size_t g = base + (size_t)(row0 + rr) * W_ + gc;
                    s[cc * HS_STR + rr] = make_float2(rdx[g], rdy[g]);
                }
            }
        }
    }
    __syncthreads();

    const int x0 = ty * 4;                   // local first output col
    float2 acc[4] = {};
    float2 win[4];
    #pragma unroll
    for (int k = 0; k < 4; ++k) win[k] = s[(x0 + k) * HS_STR + r];

    #pragma unroll
    for (int t = 0; t < KSZ; ++t) {
        float2 nxt;
        if (t < KSZ - 1) nxt = s[(x0 + t + 4) * HS_STR + r];
        const float2 w = WH2.v[t];
        #pragma unroll
        for (int j = 0; j < 4; ++j)
            fma2(acc[j], win[(t + j) & 3], w);
        if (t < KSZ - 1) win[t & 3] = nxt;
    }

    // direct transposed stores: g_tT[b][col][row]; lanes (r) contiguous -> coalesced.
    // No transpose stage, no extra __syncthreads.
    #pragma unroll
    for (int j = 0; j < 4; ++j)
        g_tT[base + (size_t)(c0 + x0 + j) * H_ + row0 + r] = acc[j];
}

// ================= kernel 2: vertical blur + warp (ring-8 conv; transposed scratch reads) =================
// Tile 32 cols x 32 rows. block (32,8): tx = col, ty = 4-row chunk.
// smem col-major s[xx*73 + y]: conflict-free per 16-lane phase.
// Halo read from g_tT: each of 32 x-cols is a contiguous 72-element y-run.
#define VS_STR 73

__global__ __launch_bounds__(256) void vwarp_kernel(
    const float* __restrict__ img, float* __restrict__ out)
{
    __shared__ float2 s[32 * VS_STR];   // 18,688 B

    const int tx = threadIdx.x;
    const int ty = threadIdx.y;          // 0..7
    const int tid = ty * 32 + tx;
    const int x0b = blockIdx.x * 32;
    const int x  = x0b + tx;
    const int y0 = blockIdx.y * 32;
    const int b  = blockIdx.z;
    const size_t base = (size_t)b * H_ * W_;
    const float2* gtT = g_tT + base;

    // halo: 32 x-cols, each a 72-row y-run (contiguous in g_tT).
    // lanes sweep y (coalesced LDG; STS word-stride 2 -> conflict-free),
    // warps sweep x (4 cols per warp).
    {
        const int lane = tid & 31;
        const int w    = tid >> 5;       // 0..7
        #pragma unroll
        for (int q = 0; q < 4; ++q) {
            const int xx = w * 4 + q;    // 0..31 local col
            const float2* col = gtT + (size_t)(x0b + xx) * H_;
            #pragma unroll
            for (int m = 0; m < 3; ++m) {
                const int j = lane + 32 * m;   // 0..95
                if (j < 72) {
                    const int y = reflect_once(y0 + j - RAD, H_);
                    s[xx * VS_STR + j] = __ldg(col + y);
                }
            }
        }
    }
    __syncthreads();

    const int r0 = ty * 4;               // first output row (tile-local)
    float2 acc[4] = {};
    // ring-8 window: refill distance 5 taps covers LDS latency
    float2 win[8];
    #pragma unroll
    for (int k = 0; k < 8; ++k) win[k] = s[tx * VS_STR + r0 + k];

    #pragma unroll
    for (int t = 0; t < KSZ; ++t) {
        float2 nxt;
        if (t < 36) nxt = s[tx * VS_STR + r0 + t + 8];
        const float2 w = WV2.v[t];
        #pragma unroll
        for (int j = 0; j < 4; ++j)
            fma2(acc[j], win[(t + j) & 7], w);
        if (t < 36) win[t & 7] = nxt;
    }

    const float* im = img + base;
    const float xbase = (float)x - 50.0f;   // fold (2*ALPHA*blur - ALPHA)

    #pragma unroll
    for (int j = 0; j < 4; ++j) {
        const int yo = y0 + r0 + j;
        const float xx = xbase + acc[j].x;
        const float yy = (float)yo - 50.0f + acc[j].y;

        const int xi = __float2int_rd(xx);
        const int yi = __float2int_rd(yy);
        const float wx = xx - (float)xi;
        const float wy = yy - (float)yi;

        const int x0r = reflect_fast(xi);
        const int x1r = reflect_fast(xi + 1);
        const int y0r = reflect_fast(yi);   // H_==W_==512
        const int y1r = reflect_fast(yi + 1);

        const float* ra = im + (size_t)y0r * W_;
        const float* rb = im + (size_t)y1r * W_;
        const float v00 = __ldg(ra + x0r);
        const float v01 = __ldg(ra + x1r);
        const float v10 = __ldg(rb + x0r);
        const float v11 = __ldg(rb + x1r);

        const float top = fmaf(wx, v01 - v00, v00);
        const float bot = fmaf(wx, v11 - v10, v10);
        out[base + (size_t)yo * W_ + x] = fmaf(wy, bot - top, top);
    }
}

// ---------------- launch ----------------
extern "C" void kernel_launch(void* const* d_in, const int* in_sizes, int n_in,
                              void* d_out, int out_size)
{
    const float* x       = (const float*)d_in[0];  // [B,1,H,W]
    const float* rand_dx = (const float*)d_in[1];  // [B,H,W]
    const float* rand_dy = (const float*)d_in[2];  // [B,H,W]
    float* out = (float*)d_out;

    {
        dim3 grid(W_ / 32, H_ / 32, B_);
        dim3 block(32, 8);
        hblur_kernel<<<grid, block>>>(rand_dx, rand_dy);
    }
    {
        dim3 grid(W_ / 32, H_ / 32, B_);
        dim3 block(32, 8);
        vwarp_kernel<<<grid, block>>>(x, out);
    }
}

// round 16
// speedup vs baseline: 1.2201x; 1.0248x over previous
#include <cuda_runtime.h>
#include <cuda_bf16.h>

// ---------------- problem constants ----------------
#define B_  64
#define H_  512
#define W_  512
#define RAD 20
#define KSZ 41

// ---------------- Gaussian weights (compile-time) ----------------
constexpr double PHI[21] = {
    1.0,
    0.98019867, 0.92311635, 0.83527021, 0.72614903, 0.60653066,
    0.48675227, 0.37531110, 0.27803730, 0.19789870, 0.13533528,
    0.08892161, 0.05613478, 0.03404747, 0.01984109, 0.01110900,
    0.00597603, 0.00308871, 0.00153381, 0.00073181, 0.00033546
};

constexpr double ksum() {
    double s = PHI[0];
    for (int t = 1; t <= 20; ++t) s += 2.0 * PHI[t];
    return s;
}

struct W41x2 { float2 v[KSZ]; };

constexpr W41x2 make_w2(double scale) {
    W41x2 w{};
    double s = ksum();
    for (int i = 0; i < KSZ; ++i) {
        int t = i - RAD; if (t < 0) t = -t;
        float f = (float)(scale * PHI[t] / s);
        w.v[i].x = f; w.v[i].y = f;
    }
    return w;
}

__constant__ W41x2 WH2 = make_w2(1.0);    // h-pass
__constant__ W41x2 WV2 = make_w2(100.0);  // v-pass folds 2*ALPHA; subtract ALPHA later

// packed f32x2 FMA (sm_100+)
__device__ __forceinline__ void fma2(float2& acc, const float2 v, const float2 w) {
    asm("fma.rn.f32x2 %0, %1, %2, %0;"
        : "+l"(reinterpret_cast<unsigned long long&>(acc))
        : "l"(reinterpret_cast<const unsigned long long&>(v)),
          "l"(reinterpret_cast<const unsigned long long&>(w)));
}

// ---------------- TRANSPOSED interleaved scratch: g_tT[b][x][y] = (dx,dy) ----------------
__device__ float2 g_tT[(size_t)B_ * H_ * W_];

__device__ __forceinline__ int reflect_once(int i, int n) {
    i = (i < 0) ? (-1 - i) : i;
    return (i >= n) ? (2 * n - 1 - i) : i;
}

// fast reflect for gather coords: valid for i in [-512, 1023], n=512
__device__ __forceinline__ int reflect_fast(int i) {
    return ((unsigned)i < (unsigned)W_) ? i : (~i & (2 * W_ - 1));
}

// ================= kernel 1: horizontal blur (64-col tile, direct transposed stores) =================
// Tile 32 rows x 64 cols (halo 104/64 = 1.625x). block (32,16) = 512 threads:
// threadIdx.x = row lane, ty = 4-col chunk. smem col-major s[cc*33 + r].
// Output stored to g_tT[x][y]: lanes = 32 consecutive y -> 256B coalesced, no transpose stage.
#define HS_STR 33

__global__ __launch_bounds__(512) void hblur_kernel(
    const float* __restrict__ rdx, const float* __restrict__ rdy)
{
    __shared__ float2 s[104 * HS_STR];   // 27,456 B -> 4 CTAs/SM

    const int r   = threadIdx.x;             // 0..31 row lane
    const int ty  = threadIdx.y;             // 0..15 col chunk (4 cols each)
    const int tid = ty * 32 + r;
    const int c0   = blockIdx.x * 64;
    const int row0 = blockIdx.y * 32;
    const int b    = blockIdx.z;
    const size_t base = (size_t)b * H_ * W_;

    // halo: 104 window cols x 32 rows; div-free, coalesced on col
    {
        const int lc = tid & 31;
        const int lr = tid >> 5;             // 0..15
        #pragma unroll
        for (int q = 0; q < 4; ++q) {
            const int cc = lc + 32 * q;
            if (cc < 104) {
                const int gc = reflect_once(c0 - RAD + cc, W_);
                #pragma unroll
                for (int m = 0; m < 2; ++m) {
                    const int rr = lr + 16 * m;
                    const size_t g = base + (size_t)(row0 + rr) * W_ + gc;
                    s[cc * HS_STR + rr] = make_float2(rdx[g], rdy[g]);
                }
            }
        }
    }
    __syncthreads();

    const int x0 = ty * 4;                   // local first output col (0..60)
    float2 acc[4] = {};
    float2 win[4];
    #pragma unroll
    for (int k = 0; k < 4; ++k) win[k] = s[(x0 + k) * HS_STR + r];

    #pragma unroll
    for (int t = 0; t < KSZ; ++t) {
        float2 nxt;
        if (t < KSZ - 1) nxt = s[(x0 + t + 4) * HS_STR + r];   // max 60+39+4=103 < 104
        const float2 w = WH2.v[t];
        #pragma unroll
        for (int j = 0; j < 4; ++j)
            fma2(acc[j], win[(t + j) & 3], w);
        if (t < KSZ - 1) win[t & 3] = nxt;
    }

    // direct transposed stores: g_tT[b][col][row]; lanes (r) contiguous -> coalesced.
    #pragma unroll
    for (int j = 0; j < 4; ++j)
        g_tT[base + (size_t)(c0 + x0 + j) * H_ + row0 + r] = acc[j];
}

// ================= kernel 2: vertical blur + warp (byte-identical to R15 champion) =================
// Tile 32 cols x 32 rows. block (32,8): tx = col, ty = 4-row chunk.
// smem col-major s[xx*73 + y]: conflict-free per 16-lane phase.
// Halo read from g_tT: each of 32 x-cols is a contiguous 72-element y-run.
#define VS_STR 73

__global__ __launch_bounds__(256) void vwarp_kernel(
    const float* __restrict__ img, float* __restrict__ out)
{
    __shared__ float2 s[32 * VS_STR];   // 18,688 B

    const int tx = threadIdx.x;
    const int ty = threadIdx.y;          // 0..7
    const int tid = ty * 32 + tx;
    const int x0b = blockIdx.x * 32;
    const int x  = x0b + tx;
    const int y0 = blockIdx.y * 32;
    const int b  = blockIdx.z;
    const size_t base = (size_t)b * H_ * W_;
    const float2* gtT = g_tT + base;

    // halo: 32 x-cols, each a 72-row y-run (contiguous in g_tT).
    {
        const int lane = tid & 31;
        const int w    = tid >> 5;       // 0..7
        #pragma unroll
        for (int q = 0; q < 4; ++q) {
            const int xx = w * 4 + q;    // 0..31 local col
            const float2* col = gtT + (size_t)(x0b + xx) * H_;
            #pragma unroll
            for (int m = 0; m < 3; ++m) {
                const int j = lane + 32 * m;   // 0..95
                if (j < 72) {
                    const int y = reflect_once(y0 + j - RAD, H_);
                    s[xx * VS_STR + j] = __ldg(col + y);
                }
            }
        }
    }
    __syncthreads();

    const int r0 = ty * 4;               // first output row (tile-local)
    float2 acc[4] = {};
    // ring-8 window: refill distance 5 taps covers LDS latency
    float2 win[8];
    #pragma unroll
    for (int k = 0; k < 8; ++k) win[k] = s[tx * VS_STR + r0 + k];

    #pragma unroll
    for (int t = 0; t < KSZ; ++t) {
        float2 nxt;
        if (t < 36) nxt = s[tx * VS_STR + r0 + t + 8];
        const float2 w = WV2.v[t];
        #pragma unroll
        for (int j = 0; j < 4; ++j)
            fma2(acc[j], win[(t + j) & 7], w);
        if (t < 36) win[t & 7] = nxt;
    }

    const float* im = img + base;
    const float xbase = (float)x - 50.0f;   // fold (2*ALPHA*blur - ALPHA)

    #pragma unroll
    for (int j = 0; j < 4; ++j) {
        const int yo = y0 + r0 + j;
        const float xx = xbase + acc[j].x;
        const float yy = (float)yo - 50.0f + acc[j].y;

        const int xi = __float2int_rd(xx);
        const int yi = __float2int_rd(yy);
        const float wx = xx - (float)xi;
        const float wy = yy - (float)yi;

        const int x0r = reflect_fast(xi);
        const int x1r = reflect_fast(xi + 1);
        const int y0r = reflect_fast(yi);   // H_==W_==512
        const int y1r = reflect_fast(yi + 1);

        const float* ra = im + (size_t)y0r * W_;
        const float* rb = im + (size_t)y1r * W_;
        const float v00 = __ldg(ra + x0r);
        const float v01 = __ldg(ra + x1r);
        const float v10 = __ldg(rb + x0r);
        const float v11 = __ldg(rb + x1r);

        const float top = fmaf(wx, v01 - v00, v00);
        const float bot = fmaf(wx, v11 - v10, v10);
        out[base + (size_t)yo * W_ + x] = fmaf(wy, bot - top, top);
    }
}

// ---------------- launch ----------------
extern "C" void kernel_launch(void* const* d_in, const int* in_sizes, int n_in,
                              void* d_out, int out_size)
{
    const float* x       = (const float*)d_in[0];  // [B,1,H,W]
    const float* rand_dx = (const float*)d_in[1];  // [B,H,W]
    const float* rand_dy = (const float*)d_in[2];  // [B,H,W]
    float* out = (float*)d_out;

    {
        dim3 grid(W_ / 64, H_ / 32, B_);
        dim3 block(32, 16);
        hblur_kernel<<<grid, block>>>(rand_dx, rand_dy);
    }
    {
        dim3 grid(W_ / 32, H_ / 32, B_);
        dim3 block(32, 8);
        vwarp_kernel<<<grid, block>>>(x, out);
    }
}

// round 17
// speedup vs baseline: 1.2461x; 1.0213x over previous
#include <cuda_runtime.h>
#include <cuda_bf16.h>

// ---------------- problem constants ----------------
#define B_  64
#define H_  512
#define W_  512
#define RAD 20
#define KSZ 41

// ---------------- Gaussian weights (compile-time) ----------------
constexpr double PHI[21] = {
    1.0,
    0.98019867, 0.92311635, 0.83527021, 0.72614903, 0.60653066,
    0.48675227, 0.37531110, 0.27803730, 0.19789870, 0.13533528,
    0.08892161, 0.05613478, 0.03404747, 0.01984109, 0.01110900,
    0.00597603, 0.00308871, 0.00153381, 0.00073181, 0.00033546
};

constexpr double ksum() {
    double s = PHI[0];
    for (int t = 1; t <= 20; ++t) s += 2.0 * PHI[t];
    return s;
}

struct W41x2 { float2 v[KSZ]; };

constexpr W41x2 make_w2(double scale) {
    W41x2 w{};
    double s = ksum();
    for (int i = 0; i < KSZ; ++i) {
        int t = i - RAD; if (t < 0) t = -t;
        float f = (float)(scale * PHI[t] / s);
        w.v[i].x = f; w.v[i].y = f;
    }
    return w;
}

__constant__ W41x2 WH2 = make_w2(1.0);    // h-pass
__constant__ W41x2 WV2 = make_w2(100.0);  // v-pass folds 2*ALPHA; subtract ALPHA later

// packed f32x2 FMA (sm_100+)
__device__ __forceinline__ void fma2(float2& acc, const float2 v, const float2 w) {
    asm("fma.rn.f32x2 %0, %1, %2, %0;"
        : "+l"(reinterpret_cast<unsigned long long&>(acc))
        : "l"(reinterpret_cast<const unsigned long long&>(v)),
          "l"(reinterpret_cast<const unsigned long long&>(w)));
}

// ---------------- TRANSPOSED interleaved scratch: g_tT[b][x][y] = (dx,dy) ----------------
__device__ float2 g_tT[(size_t)B_ * H_ * W_];

__device__ __forceinline__ int reflect_once(int i, int n) {
    i = (i < 0) ? (-1 - i) : i;
    return (i >= n) ? (2 * n - 1 - i) : i;
}

// fast reflect for gather coords: valid for i in [-512, 1023], n=512
__device__ __forceinline__ int reflect_fast(int i) {
    return ((unsigned)i < (unsigned)W_) ? i : (~i & (2 * W_ - 1));
}

// ================= kernel 1: horizontal blur (8 px/thread, 64-col tile) =================
// Tile 32 rows x 64 cols (halo 104/64 = 1.625x). block (32,8) = 256 threads:
// threadIdx.x = row lane, ty = 8-col chunk. Window: 6 smem elem/px (was 11).
// smem col-major s[cc*33 + r]; direct transposed stores to g_tT (coalesced).
#define HS_STR 33

__global__ __launch_bounds__(256) void hblur_kernel(
    const float* __restrict__ rdx, const float* __restrict__ rdy)
{
    __shared__ float2 s[104 * HS_STR];   // 27,456 B

    const int r   = threadIdx.x;             // 0..31 row lane
    const int ty  = threadIdx.y;             // 0..7 col chunk (8 cols each)
    const int tid = ty * 32 + r;
    const int c0   = blockIdx.x * 64;
    const int row0 = blockIdx.y * 32;
    const int b    = blockIdx.z;
    const size_t base = (size_t)b * H_ * W_;

    // halo: 104 window cols x 32 rows; div-free, coalesced on col
    {
        const int lc = tid & 31;
        const int lr = tid >> 5;             // 0..7
        #pragma unroll
        for (int q = 0; q < 4; ++q) {
            const int cc = lc + 32 * q;
            if (cc < 104) {
                const int gc = reflect_once(c0 - RAD + cc, W_);
                #pragma unroll
                for (int m = 0; m < 4; ++m) {
                    const int rr = lr + 8 * m;
                    const size_t g = base + (size_t)(row0 + rr) * W_ + gc;
                    s[cc * HS_STR + rr] = make_float2(rdx[g], rdy[g]);
                }
            }
        }
    }
    __syncthreads();

    const int x0 = ty * 8;                   // local first output col (0..56)
    float2 acc[8] = {};
    float2 win[8];
    #pragma unroll
    for (int k = 0; k < 8; ++k) win[k] = s[(x0 + k) * HS_STR + r];

    #pragma unroll
    for (int t = 0; t < KSZ; ++t) {
        float2 nxt;
        if (t < KSZ - 1) nxt = s[(x0 + t + 8) * HS_STR + r];   // max 56+39+8=103 < 104
        const float2 w = WH2.v[t];
        #pragma unroll
        for (int j = 0; j < 8; ++j)
            fma2(acc[j], win[(t + j) & 7], w);
        if (t < KSZ - 1) win[t & 7] = nxt;
    }

    // direct transposed stores: g_tT[b][col][row]; lanes (r) contiguous -> coalesced.
    #pragma unroll
    for (int j = 0; j < 8; ++j)
        g_tT[base + (size_t)(c0 + x0 + j) * H_ + row0 + r] = acc[j];
}

// ================= kernel 2: vertical blur + warp (byte-identical to R15/R16 champion) =================
// Tile 32 cols x 32 rows. block (32,8): tx = col, ty = 4-row chunk.
// smem col-major s[xx*73 + y]: conflict-free per 16-lane phase.
// Halo read from g_tT: each of 32 x-cols is a contiguous 72-element y-run.
#define VS_STR 73

__global__ __launch_bounds__(256) void vwarp_kernel(
    const float* __restrict__ img, float* __restrict__ out)
{
    __shared__ float2 s[32 * VS_STR];   // 18,688 B

    const int tx = threadIdx.x;
    const int ty = threadIdx.y;          // 0..7
    const int tid = ty * 32 + tx;
    const int x0b = blockIdx.x * 32;
    const int x  = x0b + tx;
    const int y0 = blockIdx.y * 32;
    const int b  = blockIdx.z;
    const size_t base = (size_t)b * H_ * W_;
    const float2* gtT = g_tT + base;

    // halo: 32 x-cols, each a 72-row y-run (contiguous in g_tT).
    {
        const int lane = tid & 31;
        const int w    = tid >> 5;       // 0..7
        #pragma unroll
        for (int q = 0; q < 4; ++q) {
            const int xx = w * 4 + q;    // 0..31 local col
            const float2* col = gtT + (size_t)(x0b + xx) * H_;
            #pragma unroll
            for (int m = 0; m < 3; ++m) {
                const int j = lane + 32 * m;   // 0..95
                if (j < 72) {
                    const int y = reflect_once(y0 + j - RAD, H_);
                    s[xx * VS_STR + j] = __ldg(col + y);
                }
            }
        }
    }
    __syncthreads();

    const int r0 = ty * 4;               // first output row (tile-local)
    float2 acc[4] = {};
    // ring-8 window: refill distance 5 taps covers LDS latency
    float2 win[8];
    #pragma unroll
    for (int k = 0; k < 8; ++k) win[k] = s[tx * VS_STR + r0 + k];

    #pragma unroll
    for (int t = 0; t < KSZ; ++t) {
        float2 nxt;
        if (t < 36) nxt = s[tx * VS_STR + r0 + t + 8];
        const float2 w = WV2.v[t];
        #pragma unroll
        for (int j = 0; j < 4; ++j)
            fma2(acc[j], win[(t + j) & 7], w);
        if (t < 36) win[t & 7] = nxt;
    }

    const float* im = img + base;
    const float xbase = (float)x - 50.0f;   // fold (2*ALPHA*blur - ALPHA)

    #pragma unroll
    for (int j = 0; j < 4; ++j) {
        const int yo = y0 + r0 + j;
        const float xx = xbase + acc[j].x;
        const float yy = (float)yo - 50.0f + acc[j].y;

        const int xi = __float2int_rd(xx);
        const int yi = __float2int_rd(yy);
        const float wx = xx - (float)xi;
        const float wy = yy - (float)yi;

        const int x0r = reflect_fast(xi);
        const int x1r = reflect_fast(xi + 1);
        const int y0r = reflect_fast(yi);   // H_==W_==512
        const int y1r = reflect_fast(yi + 1);

        const float* ra = im + (size_t)y0r * W_;
        const float* rb = im + (size_t)y1r * W_;
        const float v00 = __ldg(ra + x0r);
        const float v01 = __ldg(ra + x1r);
        const float v10 = __ldg(rb + x0r);
        const float v11 = __ldg(rb + x1r);

        const float top = fmaf(wx, v01 - v00, v00);
        const float bot = fmaf(wx, v11 - v10, v10);
        out[base + (size_t)yo * W_ + x] = fmaf(wy, bot - top, top);
    }
}

// ---------------- launch ----------------
extern "C" void kernel_launch(void* const* d_in, const int* in_sizes, int n_in,
                              void* d_out, int out_size)
{
    const float* x       = (const float*)d_in[0];  // [B,1,H,W]
    const float* rand_dx = (const float*)d_in[1];  // [B,H,W]
    const float* rand_dy = (const float*)d_in[2];  // [B,H,W]
    float* out = (float*)d_out;

    {
        dim3 grid(W_ / 64, H_ / 32, B_);
        dim3 block(32, 8);
        hblur_kernel<<<grid, block>>>(rand_dx, rand_dy);
    }
    {
        dim3 grid(W_ / 32, H_ / 32, B_);
        dim3 block(32, 8);
        vwarp_kernel<<<grid, block>>>(x, out);
    }
}